// round 8
// baseline (speedup 1.0000x reference)
#include <cuda_runtime.h>
#include <cuda_bf16.h>
#include <cstdint>

// Problem dims
#define BB   32
#define TT   2048
#define FF   64
#define HH   256
#define OUTD 64
#define ROWS (BB*TT)          // 65536
#define G3   (3*HH)           // 768
#define TK   32               // proj k-chunk

// ---------------- scratch (static device globals; no allocation) ----------------
__device__ float g_xn [ (size_t)ROWS * FF ];     // 16 MB  LayerNorm output
__device__ float g_xbR[ (size_t)ROWS * G3 ];     // 192 MB rearranged xb (reused by both GRUs)
__device__ float g_h1 [ (size_t)ROWS * HH ];     // 64 MB  GRU1 sequence output

// ---------------- helpers ----------------
__device__ __forceinline__ uint32_t smem_u32(const void* p) {
    uint32_t a;
    asm("{ .reg .u64 t; cvta.to.shared.u64 t, %1; cvt.u32.u64 %0, t; }" : "=r"(a) : "l"(p));
    return a;
}
__device__ __forceinline__ unsigned long long pack2(float lo, float hi) {
    unsigned long long r;
    asm("mov.b64 %0, {%1, %2};" : "=l"(r) : "f"(lo), "f"(hi));
    return r;
}
__device__ __forceinline__ unsigned long long fma2(unsigned long long a, unsigned long long b,
                                                   unsigned long long c) {
    unsigned long long d;
    asm("fma.rn.f32x2 %0, %1, %2, %3;" : "=l"(d) : "l"(a), "l"(b), "l"(c));
    return d;
}
__device__ __forceinline__ unsigned long long add2(unsigned long long a, unsigned long long b) {
    unsigned long long d;
    asm("add.rn.f32x2 %0, %1, %2;" : "=l"(d) : "l"(a), "l"(b));
    return d;
}
__device__ __forceinline__ float hsum2(unsigned long long a) {
    float lo, hi;
    asm("mov.b64 {%0, %1}, %2;" : "=f"(lo), "=f"(hi) : "l"(a));
    return lo + hi;
}
__device__ __forceinline__ void unpack2(unsigned long long a, float& lo, float& hi) {
    asm("mov.b64 {%0, %1}, %2;" : "=f"(lo), "=f"(hi) : "l"(a));
}
__device__ __forceinline__ float tanh_fast(float x) {
    float y;
    asm("tanh.approx.f32 %0, %1;" : "=f"(y) : "f"(x));
    return y;
}
__device__ __forceinline__ float sigmoid_fast(float x) {
    return 0.5f * tanh_fast(0.5f * x) + 0.5f;
}
__device__ __forceinline__ void mbar_init(uint32_t a, uint32_t cnt) {
    asm volatile("mbarrier.init.shared.b64 [%0], %1;" :: "r"(a), "r"(cnt) : "memory");
}
__device__ __forceinline__ void mbar_expect(uint32_t a, uint32_t tx) {
    asm volatile("mbarrier.arrive.expect_tx.shared.b64 _, [%0], %1;" :: "r"(a), "r"(tx) : "memory");
}
__device__ __forceinline__ void mbar_wait(uint32_t addr, int phase) {
    asm volatile(
        "{\n\t.reg .pred P;\n\t"
        "WL_%=:\n\t"
        "mbarrier.try_wait.parity.acquire.cta.shared::cta.b64 P, [%0], %1, 0x989680;\n\t"
        "@P bra.uni WD_%=;\n\t"
        "bra.uni WL_%=;\n\t"
        "WD_%=:\n\t}"
        :: "r"(addr), "r"(phase) : "memory");
}
__device__ __forceinline__ uint32_t mapa_u32(uint32_t a, uint32_t rnk) {
    uint32_t r;
    asm("mapa.shared::cluster.u32 %0, %1, %2;" : "=r"(r) : "r"(a), "r"(rnk));
    return r;
}
__device__ __forceinline__ void bulk_put(uint32_t dst_cluster, uint32_t src_cta,
                                         uint32_t bytes, uint32_t mbar_cluster) {
    asm volatile(
        "cp.async.bulk.shared::cluster.shared::cta.mbarrier::complete_tx::bytes "
        "[%0], [%1], %2, [%3];"
        :: "r"(dst_cluster), "r"(src_cta), "r"(bytes), "r"(mbar_cluster) : "memory");
}

// ---------------- LayerNorm: one warp per row of 64 ----------------
__global__ __launch_bounds__(256) void ln_kernel(
    const float* __restrict__ x, const float* __restrict__ gamma,
    const float* __restrict__ beta)
{
    int warp = (blockIdx.x * blockDim.x + threadIdx.x) >> 5;
    int lane = threadIdx.x & 31;
    if (warp >= ROWS) return;
    const float* row = x + (size_t)warp * FF;
    float2 v = *(const float2*)&row[lane * 2];
    float s = v.x + v.y;
    #pragma unroll
    for (int o = 16; o; o >>= 1) s += __shfl_xor_sync(~0u, s, o);
    float mu = s * (1.f / 64.f);
    float d0 = v.x - mu, d1 = v.y - mu;
    float q = d0 * d0 + d1 * d1;
    #pragma unroll
    for (int o = 16; o; o >>= 1) q += __shfl_xor_sync(~0u, q, o);
    float rs = rsqrtf(q * (1.f / 64.f) + 1e-3f);
    float2 g  = *(const float2*)&gamma[lane * 2];
    float2 bb = *(const float2*)&beta[lane * 2];
    float2 o2;
    o2.x = d0 * rs * g.x + bb.x;
    o2.y = d1 * rs * g.y + bb.y;
    *(float2*)&g_xn[(size_t)warp * FF + lane * 2] = o2;
}

// ---------------- projection GEMM: C[ROWS,768] = A[ROWS,K] @ W[K,768] + bias ----------------
// Tile 128 rows x 128 cols, k-chunk 32, 256 threads, 8m x 8n per thread (packed-m f32x2).
// Global loads staged through registers (prefetch next chunk during compute).
// Output rearranged: g_xbR[(b*4+rank)*T + t][gate*64 + unit%64] (8 consecutive -> float4 x2).
__global__ __launch_bounds__(256) void proj_kernel(
    int K, int use_h1, const float* __restrict__ W, const float* __restrict__ bias)
{
    __shared__ float As[TK][132];  // [k][m] transposed
    __shared__ float Ws[TK][128];  // [k][n]

    const float* A = use_h1 ? g_h1 : g_xn;
    int cb = blockIdx.x * 128;
    int rb = blockIdx.y * 128;
    int tid  = threadIdx.x;
    int trow = tid >> 4;        // 0..15  (m group of 8)
    int tcol = tid & 15;        // 0..15  (n group of 8)

    // load indices
    int arow = tid >> 3;         // 0..31
    int akq  = (tid & 7) * 4;    // k offset within chunk
    int wkr  = tid >> 5;         // 0..7
    int wc4  = (tid & 31) * 4;   // n offset

    unsigned long long acc[4][8];  // [m-pair][n]
    #pragma unroll
    for (int i = 0; i < 4; i++)
        #pragma unroll
        for (int j = 0; j < 8; j++) acc[i][j] = 0ULL;

    float4 ra[4], rw[4];
    // prefetch chunk 0
    #pragma unroll
    for (int it = 0; it < 4; it++)
        ra[it] = *(const float4*)&A[(size_t)(rb + arow + it * 32) * K + akq];
    #pragma unroll
    for (int it = 0; it < 4; it++)
        rw[it] = *(const float4*)&W[(size_t)(wkr + it * 8) * G3 + cb + wc4];

    for (int kk = 0; kk < K; kk += TK) {
        // stage regs -> smem
        #pragma unroll
        for (int it = 0; it < 4; it++) {
            int r = arow + it * 32;
            As[akq + 0][r] = ra[it].x;
            As[akq + 1][r] = ra[it].y;
            As[akq + 2][r] = ra[it].z;
            As[akq + 3][r] = ra[it].w;
            *(float4*)&Ws[wkr + it * 8][wc4] = rw[it];
        }
        __syncthreads();
        // prefetch next chunk (regs are free; latency hidden under compute)
        if (kk + TK < K) {
            #pragma unroll
            for (int it = 0; it < 4; it++)
                ra[it] = *(const float4*)&A[(size_t)(rb + arow + it * 32) * K + kk + TK + akq];
            #pragma unroll
            for (int it = 0; it < 4; it++)
                rw[it] = *(const float4*)&W[(size_t)(kk + TK + wkr + it * 8) * G3 + cb + wc4];
        }
        #pragma unroll 8
        for (int k = 0; k < TK; k++) {
            const ulonglong2* ap = (const ulonglong2*)&As[k][trow * 8];
            ulonglong2 a01 = ap[0], a23 = ap[1];
            float4 b0 = *(const float4*)&Ws[k][tcol * 8];
            float4 b1 = *(const float4*)&Ws[k][tcol * 8 + 4];
            unsigned long long bb[8];
            bb[0] = pack2(b0.x, b0.x); bb[1] = pack2(b0.y, b0.y);
            bb[2] = pack2(b0.z, b0.z); bb[3] = pack2(b0.w, b0.w);
            bb[4] = pack2(b1.x, b1.x); bb[5] = pack2(b1.y, b1.y);
            bb[6] = pack2(b1.z, b1.z); bb[7] = pack2(b1.w, b1.w);
            #pragma unroll
            for (int j = 0; j < 8; j++) {
                acc[0][j] = fma2(a01.x, bb[j], acc[0][j]);
                acc[1][j] = fma2(a01.y, bb[j], acc[1][j]);
                acc[2][j] = fma2(a23.x, bb[j], acc[2][j]);
                acc[3][j] = fma2(a23.y, bb[j], acc[3][j]);
            }
        }
        __syncthreads();
    }

    // epilogue: bias + rearranged float4 stores (8 consecutive cc per row)
    int g0   = cb + tcol * 8;
    int gate = g0 >> 8;
    int unit = g0 & 255;
    int rnk  = unit >> 6;
    int cc   = gate * 64 + (unit & 63);
    float bv[8];
    #pragma unroll
    for (int j = 0; j < 8; j++) bv[j] = bias[g0 + j];

    #pragma unroll
    for (int i2 = 0; i2 < 4; i2++) {
        float r0[8], r1[8];
        #pragma unroll
        for (int j = 0; j < 8; j++) {
            unpack2(acc[i2][j], r0[j], r1[j]);
            r0[j] += bv[j]; r1[j] += bv[j];
        }
        #pragma unroll
        for (int half = 0; half < 2; half++) {
            int row = rb + trow * 8 + 2 * i2 + half;
            int b   = row >> 11;
            int t   = row & 2047;
            float* dst = g_xbR + (((size_t)(b * 4 + rnk)) * TT + t) * 192 + cc;
            const float* rv = half ? r1 : r0;
            *(float4*)dst       = make_float4(rv[0], rv[1], rv[2], rv[3]);
            *(float4*)(dst + 4) = make_float4(rv[4], rv[5], rv[6], rv[7]);
        }
    }
}

// ---------------- GRU recurrence: cluster of 4 CTAs per batch ----------------
// 384 threads: q = tid/192 (k-half of 128), c = tid%192 (gate*64+unit).
// R slice in packed f32x2 registers; h double-buffered in SMEM.
// Cross-CTA exchange: gates write to local staging, one elected thread issues
// 4x cp.async.bulk (256 B) to the cluster CTAs' h buffer + mbar (4 tx events/step).
__global__ void __cluster_dims__(4, 1, 1) __launch_bounds__(384, 1)
gru_kernel(const float* __restrict__ rk, const float* __restrict__ rbias,
           const float* __restrict__ wd, const float* __restrict__ bd,
           float* __restrict__ out, int flags)  // bit0: write seq to g_h1, bit1: dense head
{
    __shared__ __align__(16) float h_sh[2][256];
    __shared__ __align__(16) float stage[2][64];
    __shared__ float partial[2][192];
    __shared__ __align__(8) unsigned long long mbar[2];

    int tid  = threadIdx.x;
    int rank = blockIdx.x;      // cluster rank
    int b    = blockIdx.y;
    int q    = tid / 192;
    int c    = tid % 192;
    int gate = c >> 6;
    int u    = c & 63;
    int gcol = gate * 256 + rank * 64 + u;

    // load R slice into packed registers: R2[i] = (rk[2i], rk[2i+1]) down column gcol
    unsigned long long R2[64];
    #pragma unroll
    for (int i = 0; i < 64; i++) {
        float lo = rk[(size_t)(q * 128 + 2 * i)     * G3 + gcol];
        float hi = rk[(size_t)(q * 128 + 2 * i + 1) * G3 + gcol];
        R2[i] = pack2(lo, hi);
    }

    uint32_t mb0 = smem_u32(&mbar[0]);
    uint32_t mb1 = smem_u32(&mbar[1]);
    uint32_t hb  = smem_u32(&h_sh[0][0]);
    uint32_t stb = smem_u32(&stage[0][0]);

    if (tid == 0) {
        mbar_init(mb0, 1);
        mbar_init(mb1, 1);
        mbar_expect(mb1, 1024);   // X_1 (delivered during step 0)
    }
    for (int i = tid; i < 256; i += 384) h_sh[0][i] = 0.f;  // h_0 = 0 in buf 0
    __syncthreads();
    asm volatile("barrier.cluster.arrive.aligned;" ::: "memory");
    asm volatile("barrier.cluster.wait.aligned;"   ::: "memory");

    const float* xb = g_xbR + ((size_t)(b * 4 + rank)) * TT * 192;
    float rbz = 0.f, rbr = 0.f, rbh = 0.f, xz = 0.f, xr = 0.f, xh = 0.f;
    uint32_t rmb[4], rhb[4];  // remote mbar[0] / h_sh base per target CTA
    if (tid < 64) {
        rbz = rbias[rank * 64 + tid];
        rbr = rbias[256 + rank * 64 + tid];
        rbh = rbias[512 + rank * 64 + tid];
        xz = xb[tid]; xr = xb[64 + tid]; xh = xb[128 + tid];
        #pragma unroll
        for (int tg = 0; tg < 4; tg++) {
            rmb[tg] = mapa_u32(mb0, tg);
            rhb[tg] = mapa_u32(hb, tg);
        }
    }

    float* seqp = g_h1 + ((size_t)b * TT) * HH + rank * 64;
    int ph0 = 0, ph1 = 0;

    for (int t = 0; t < TT; t++) {
        int k = t & 1;                       // h_t lives in buf[k], exchange on mbar[k]
        if (t) {
            if (k) { mbar_wait(mb1, ph1); ph1 ^= 1; }
            else   { mbar_wait(mb0, ph0); ph0 ^= 1; }
        }
        if (tid == 0 && t + 2 <= TT)
            mbar_expect(k ? mb1 : mb0, 1024);   // X_{t+2} on same mbar

        // ---- inner product: 64 packed fma2 per thread
        const ulonglong2* h4 = (const ulonglong2*)&h_sh[k][q * 128];
        unsigned long long a0 = 0ULL, a1 = 0ULL, a2 = 0ULL, a3 = 0ULL;
        #pragma unroll
        for (int i = 0; i < 16; i++) {
            ulonglong2 hv1 = h4[2 * i];
            ulonglong2 hv2 = h4[2 * i + 1];
            a0 = fma2(R2[4 * i + 0], hv1.x, a0);
            a1 = fma2(R2[4 * i + 1], hv1.y, a1);
            a2 = fma2(R2[4 * i + 2], hv2.x, a2);
            a3 = fma2(R2[4 * i + 3], hv2.y, a3);
        }
        partial[q][c] = hsum2(add2(add2(a0, a1), add2(a2, a3)));
        __syncthreads();

        if (tid < 64) {
            // prefetch next step's xb (hidden behind gates + exchange)
            float nxz = 0.f, nxr = 0.f, nxh = 0.f;
            if (t + 1 < TT) {
                const float* nxb = xb + (size_t)(t + 1) * 192;
                nxz = nxb[tid]; nxr = nxb[64 + tid]; nxh = nxb[128 + tid];
            }
            float rz = partial[0][tid]       + partial[1][tid]       + rbz;
            float rr = partial[0][64 + tid]  + partial[1][64 + tid]  + rbr;
            float rh = partial[0][128 + tid] + partial[1][128 + tid] + rbh;
            float z  = sigmoid_fast(xz + rz);
            float r  = sigmoid_fast(xr + rr);
            float hh = tanh_fast(xh + r * rh);
            float hp = h_sh[k][rank * 64 + tid];
            float hn = z * hp + (1.f - z) * hh;

            if (flags & 1) seqp[(size_t)t * HH + tid] = hn;
            stage[k ^ 1][tid] = hn;
            xz = nxz; xr = nxr; xh = nxh;

            // barrier among the 64 writer threads (warps 0-1), then bulk-put
            asm volatile("bar.sync 1, 64;" ::: "memory");
            if (tid == 0 && ((flags & 2) || t + 1 < TT)) {
                asm volatile("fence.proxy.async.shared::cta;" ::: "memory");
                uint32_t src  = stb + (uint32_t)((k ^ 1) * 256);
                uint32_t boff = (uint32_t)(((k ^ 1) * 256 + rank * 64) << 2);
                uint32_t moff = (uint32_t)((k ^ 1) * 8);
                #pragma unroll
                for (int tg = 0; tg < 4; tg++)
                    bulk_put(rhb[tg] + boff, src, 256, rmb[tg] + moff);
            }
        }
        // no CTA-wide barrier: the next mbar_wait provides the sync
    }

    // dense head (GRU2): wait final exchange X_TT (on mbar[0], parity ph0)
    if (flags & 2) {
        mbar_wait(mb0, ph0);
        if (rank == 0 && tid < 64) {
            float acc = bd[tid];
            #pragma unroll 8
            for (int kk2 = 0; kk2 < 256; kk2++) acc += h_sh[0][kk2] * wd[kk2 * 64 + tid];
            out[b * 64 + tid] = acc;
        }
    }
}

// ---------------- launch ----------------
extern "C" void kernel_launch(void* const* d_in, const int* in_sizes, int n_in,
                              void* d_out, int out_size)
{
    const float* x     = (const float*)d_in[0];
    const float* gamma = (const float*)d_in[1];
    const float* beta  = (const float*)d_in[2];
    const float* k1    = (const float*)d_in[3];
    const float* rk1   = (const float*)d_in[4];
    const float* b1    = (const float*)d_in[5];   // [2,768]
    const float* k2    = (const float*)d_in[6];
    const float* rk2   = (const float*)d_in[7];
    const float* b2    = (const float*)d_in[8];   // [2,768]
    const float* wd    = (const float*)d_in[9];
    const float* bd    = (const float*)d_in[10];
    float* out = (float*)d_out;

    (void)in_sizes; (void)n_in; (void)out_size;

    ln_kernel<<<ROWS / 8, 256>>>(x, gamma, beta);
    proj_kernel<<<dim3(G3 / 128, ROWS / 128), 256>>>(FF, 0, k1, b1);
    gru_kernel<<<dim3(4, BB), 384>>>(rk1, b1 + G3, wd, bd, out, /*flags=*/1);
    proj_kernel<<<dim3(G3 / 128, ROWS / 128), 256>>>(HH, 1, k2, b2);
    gru_kernel<<<dim3(4, BB), 384>>>(rk2, b2 + G3, wd, bd, out, /*flags=*/2);
}

// round 11
// speedup vs baseline: 1.0238x; 1.0238x over previous
#include <cuda_runtime.h>
#include <cuda_bf16.h>
#include <cstdint>

// Problem dims
#define BB   32
#define TT   2048
#define FF   64
#define HH   256
#define OUTD 64
#define ROWS (BB*TT)          // 65536
#define G3   (3*HH)           // 768
#define TK   32               // proj k-chunk

// ---------------- scratch (static device globals; no allocation) ----------------
__device__ float g_xn [ (size_t)ROWS * FF ];     // 16 MB  LayerNorm output
__device__ float g_xbR[ (size_t)ROWS * G3 ];     // 192 MB rearranged xb (reused by both GRUs)
__device__ float g_h1 [ (size_t)ROWS * HH ];     // 64 MB  GRU1 sequence output

// ---------------- helpers ----------------
__device__ __forceinline__ uint32_t smem_u32(const void* p) {
    uint32_t a;
    asm("{ .reg .u64 t; cvta.to.shared.u64 t, %1; cvt.u32.u64 %0, t; }" : "=r"(a) : "l"(p));
    return a;
}
__device__ __forceinline__ unsigned long long pack2(float lo, float hi) {
    unsigned long long r;
    asm("mov.b64 %0, {%1, %2};" : "=l"(r) : "f"(lo), "f"(hi));
    return r;
}
__device__ __forceinline__ unsigned long long fma2(unsigned long long a, unsigned long long b,
                                                   unsigned long long c) {
    unsigned long long d;
    asm("fma.rn.f32x2 %0, %1, %2, %3;" : "=l"(d) : "l"(a), "l"(b), "l"(c));
    return d;
}
__device__ __forceinline__ unsigned long long add2(unsigned long long a, unsigned long long b) {
    unsigned long long d;
    asm("add.rn.f32x2 %0, %1, %2;" : "=l"(d) : "l"(a), "l"(b));
    return d;
}
__device__ __forceinline__ float hsum2(unsigned long long a) {
    float lo, hi;
    asm("mov.b64 {%0, %1}, %2;" : "=f"(lo), "=f"(hi) : "l"(a));
    return lo + hi;
}
__device__ __forceinline__ void unpack2(unsigned long long a, float& lo, float& hi) {
    asm("mov.b64 {%0, %1}, %2;" : "=f"(lo), "=f"(hi) : "l"(a));
}
__device__ __forceinline__ float tanh_fast(float x) {
    float y;
    asm("tanh.approx.f32 %0, %1;" : "=f"(y) : "f"(x));
    return y;
}
__device__ __forceinline__ float sigmoid_fast(float x) {
    return 0.5f * tanh_fast(0.5f * x) + 0.5f;
}
__device__ __forceinline__ void mbar_init(uint32_t a, uint32_t cnt) {
    asm volatile("mbarrier.init.shared.b64 [%0], %1;" :: "r"(a), "r"(cnt) : "memory");
}
__device__ __forceinline__ void mbar_expect(uint32_t a, uint32_t tx) {
    asm volatile("mbarrier.arrive.expect_tx.shared.b64 _, [%0], %1;" :: "r"(a), "r"(tx) : "memory");
}
__device__ __forceinline__ void mbar_wait(uint32_t addr, int phase) {
    asm volatile(
        "{\n\t.reg .pred P;\n\t"
        "WL_%=:\n\t"
        "mbarrier.try_wait.parity.acquire.cta.shared::cta.b64 P, [%0], %1, 0x989680;\n\t"
        "@P bra.uni WD_%=;\n\t"
        "bra.uni WL_%=;\n\t"
        "WD_%=:\n\t}"
        :: "r"(addr), "r"(phase) : "memory");
}
__device__ __forceinline__ uint32_t mapa_u32(uint32_t a, uint32_t rnk) {
    uint32_t r;
    asm("mapa.shared::cluster.u32 %0, %1, %2;" : "=r"(r) : "r"(a), "r"(rnk));
    return r;
}
__device__ __forceinline__ void st_async_v4(uint32_t addr, float4 v, uint32_t mbar) {
    asm volatile(
        "st.async.weak.shared::cluster.mbarrier::complete_tx::bytes.v4.b32 "
        "[%0], {%1, %2, %3, %4}, [%5];"
        :: "r"(addr), "f"(v.x), "f"(v.y), "f"(v.z), "f"(v.w), "r"(mbar) : "memory");
}

// ---------------- LayerNorm: one warp per row of 64 ----------------
__global__ __launch_bounds__(256) void ln_kernel(
    const float* __restrict__ x, const float* __restrict__ gamma,
    const float* __restrict__ beta)
{
    int warp = (blockIdx.x * blockDim.x + threadIdx.x) >> 5;
    int lane = threadIdx.x & 31;
    if (warp >= ROWS) return;
    const float* row = x + (size_t)warp * FF;
    float2 v = *(const float2*)&row[lane * 2];
    float s = v.x + v.y;
    #pragma unroll
    for (int o = 16; o; o >>= 1) s += __shfl_xor_sync(~0u, s, o);
    float mu = s * (1.f / 64.f);
    float d0 = v.x - mu, d1 = v.y - mu;
    float q = d0 * d0 + d1 * d1;
    #pragma unroll
    for (int o = 16; o; o >>= 1) q += __shfl_xor_sync(~0u, q, o);
    float rs = rsqrtf(q * (1.f / 64.f) + 1e-3f);
    float2 g  = *(const float2*)&gamma[lane * 2];
    float2 bb = *(const float2*)&beta[lane * 2];
    float2 o2;
    o2.x = d0 * rs * g.x + bb.x;
    o2.y = d1 * rs * g.y + bb.y;
    *(float2*)&g_xn[(size_t)warp * FF + lane * 2] = o2;
}

// ---------------- projection GEMM: C[ROWS,768] = A[ROWS,K] @ W[K,768] + bias ----------------
// Tile 128 rows x 128 cols, k-chunk 32, 256 threads, 8m x 8n per thread (packed-m f32x2).
// __launch_bounds__(256,2): cap 128 regs so 2 CTAs/SM (R7 had 131 regs -> occ 12.5%).
__global__ __launch_bounds__(256, 2) void proj_kernel(
    int K, int use_h1, const float* __restrict__ W, const float* __restrict__ bias)
{
    __shared__ float As[TK][132];  // [k][m] transposed
    __shared__ float Ws[TK][128];  // [k][n]

    const float* A = use_h1 ? g_h1 : g_xn;
    int cb = blockIdx.x * 128;
    int rb = blockIdx.y * 128;
    int tid  = threadIdx.x;
    int trow = tid >> 4;        // 0..15  (m group of 8)
    int tcol = tid & 15;        // 0..15  (n group of 8)

    // load indices
    int arow = tid >> 3;         // 0..31
    int akq  = (tid & 7) * 4;    // k offset within chunk
    int wkr  = tid >> 5;         // 0..7
    int wc4  = (tid & 31) * 4;   // n offset

    unsigned long long acc[4][8];  // [m-pair][n]
    #pragma unroll
    for (int i = 0; i < 4; i++)
        #pragma unroll
        for (int j = 0; j < 8; j++) acc[i][j] = 0ULL;

    float4 ra[4], rw[4];
    // prefetch chunk 0
    #pragma unroll
    for (int it = 0; it < 4; it++)
        ra[it] = *(const float4*)&A[(size_t)(rb + arow + it * 32) * K + akq];
    #pragma unroll
    for (int it = 0; it < 4; it++)
        rw[it] = *(const float4*)&W[(size_t)(wkr + it * 8) * G3 + cb + wc4];

    for (int kk = 0; kk < K; kk += TK) {
        // stage regs -> smem
        #pragma unroll
        for (int it = 0; it < 4; it++) {
            int r = arow + it * 32;
            As[akq + 0][r] = ra[it].x;
            As[akq + 1][r] = ra[it].y;
            As[akq + 2][r] = ra[it].z;
            As[akq + 3][r] = ra[it].w;
            *(float4*)&Ws[wkr + it * 8][wc4] = rw[it];
        }
        __syncthreads();
        // prefetch next chunk
        if (kk + TK < K) {
            #pragma unroll
            for (int it = 0; it < 4; it++)
                ra[it] = *(const float4*)&A[(size_t)(rb + arow + it * 32) * K + kk + TK + akq];
            #pragma unroll
            for (int it = 0; it < 4; it++)
                rw[it] = *(const float4*)&W[(size_t)(kk + TK + wkr + it * 8) * G3 + cb + wc4];
        }
        #pragma unroll 8
        for (int k = 0; k < TK; k++) {
            const ulonglong2* ap = (const ulonglong2*)&As[k][trow * 8];
            ulonglong2 a01 = ap[0], a23 = ap[1];
            float4 b0 = *(const float4*)&Ws[k][tcol * 8];
            float4 b1 = *(const float4*)&Ws[k][tcol * 8 + 4];
            unsigned long long bb[8];
            bb[0] = pack2(b0.x, b0.x); bb[1] = pack2(b0.y, b0.y);
            bb[2] = pack2(b0.z, b0.z); bb[3] = pack2(b0.w, b0.w);
            bb[4] = pack2(b1.x, b1.x); bb[5] = pack2(b1.y, b1.y);
            bb[6] = pack2(b1.z, b1.z); bb[7] = pack2(b1.w, b1.w);
            #pragma unroll
            for (int j = 0; j < 8; j++) {
                acc[0][j] = fma2(a01.x, bb[j], acc[0][j]);
                acc[1][j] = fma2(a01.y, bb[j], acc[1][j]);
                acc[2][j] = fma2(a23.x, bb[j], acc[2][j]);
                acc[3][j] = fma2(a23.y, bb[j], acc[3][j]);
            }
        }
        __syncthreads();
    }

    // epilogue: bias + rearranged float4 stores (8 consecutive cc per row)
    int g0   = cb + tcol * 8;
    int gate = g0 >> 8;
    int unit = g0 & 255;
    int rnk  = unit >> 6;
    int cc   = gate * 64 + (unit & 63);
    float bv[8];
    #pragma unroll
    for (int j = 0; j < 8; j++) bv[j] = bias[g0 + j];

    #pragma unroll
    for (int i2 = 0; i2 < 4; i2++) {
        float r0[8], r1[8];
        #pragma unroll
        for (int j = 0; j < 8; j++) {
            unpack2(acc[i2][j], r0[j], r1[j]);
            r0[j] += bv[j]; r1[j] += bv[j];
        }
        #pragma unroll
        for (int half = 0; half < 2; half++) {
            int row = rb + trow * 8 + 2 * i2 + half;
            int b   = row >> 11;
            int t   = row & 2047;
            float* dst = g_xbR + (((size_t)(b * 4 + rnk)) * TT + t) * 192 + cc;
            const float* rv = half ? r1 : r0;
            *(float4*)dst       = make_float4(rv[0], rv[1], rv[2], rv[3]);
            *(float4*)(dst + 4) = make_float4(rv[4], rv[5], rv[6], rv[7]);
        }
    }
}

// ---------------- GRU recurrence: cluster of 4 CTAs per batch ----------------
// 384 threads: q = tid/192 (k-half of 128), c = tid%192 (gate*64+unit).
// R slice in packed f32x2 registers; h double-buffered in SMEM.
// Cross-CTA exchange (R5 structure): gates shuffle-pack 4 h values into float4,
// every 4th lane sends st.async.v4 to the 4 CTAs (16 senders x 4 = 64 msgs/step,
// 64 mbar events per remote barrier instead of 256).
__global__ void __cluster_dims__(4, 1, 1) __launch_bounds__(384, 1)
gru_kernel(const float* __restrict__ rk, const float* __restrict__ rbias,
           const float* __restrict__ wd, const float* __restrict__ bd,
           float* __restrict__ out, int flags)  // bit0: write seq to g_h1, bit1: dense head
{
    __shared__ __align__(16) float h_sh[2][256];
    __shared__ float partial[2][192];
    __shared__ __align__(8) unsigned long long mbar[2];

    int tid  = threadIdx.x;
    int rank = blockIdx.x;      // cluster rank
    int b    = blockIdx.y;
    int q    = tid / 192;
    int c    = tid % 192;
    int gate = c >> 6;
    int u    = c & 63;
    int gcol = gate * 256 + rank * 64 + u;

    // load R slice into packed registers: R2[i] = (rk[2i], rk[2i+1]) down column gcol
    unsigned long long R2[64];
    #pragma unroll
    for (int i = 0; i < 64; i++) {
        float lo = rk[(size_t)(q * 128 + 2 * i)     * G3 + gcol];
        float hi = rk[(size_t)(q * 128 + 2 * i + 1) * G3 + gcol];
        R2[i] = pack2(lo, hi);
    }

    uint32_t mb0 = smem_u32(&mbar[0]);
    uint32_t mb1 = smem_u32(&mbar[1]);
    uint32_t hb  = smem_u32(&h_sh[0][0]);

    if (tid == 0) {
        mbar_init(mb0, 1);
        mbar_init(mb1, 1);
        mbar_expect(mb1, 1024);   // X_1 (delivered during step 0)
    }
    for (int i = tid; i < 256; i += 384) h_sh[0][i] = 0.f;  // h_0 = 0 in buf 0
    __syncthreads();
    asm volatile("barrier.cluster.arrive.aligned;" ::: "memory");
    asm volatile("barrier.cluster.wait.aligned;"   ::: "memory");

    const float* xb = g_xbR + ((size_t)(b * 4 + rank)) * TT * 192;
    float rbz = 0.f, rbr = 0.f, rbh = 0.f, xz = 0.f, xr = 0.f, xh = 0.f;
    uint32_t rmb[4], rhb[4];  // remote mbar[0] / h_sh base per target CTA
    if (tid < 64) {
        rbz = rbias[rank * 64 + tid];
        rbr = rbias[256 + rank * 64 + tid];
        rbh = rbias[512 + rank * 64 + tid];
        xz = xb[tid]; xr = xb[64 + tid]; xh = xb[128 + tid];
        #pragma unroll
        for (int tg = 0; tg < 4; tg++) {
            rmb[tg] = mapa_u32(mb0, tg);
            rhb[tg] = mapa_u32(hb, tg);
        }
    }

    float* seqp = g_h1 + ((size_t)b * TT) * HH + rank * 64;
    int ph0 = 0, ph1 = 0;

    for (int t = 0; t < TT; t++) {
        int k = t & 1;                       // h_t lives in buf[k], exchange on mbar[k]
        if (t) {
            if (k) { mbar_wait(mb1, ph1); ph1 ^= 1; }
            else   { mbar_wait(mb0, ph0); ph0 ^= 1; }
        }
        if (tid == 0 && t + 2 <= TT)
            mbar_expect(k ? mb1 : mb0, 1024);   // X_{t+2} on same mbar

        // ---- inner product: 64 packed fma2 per thread
        const ulonglong2* h4 = (const ulonglong2*)&h_sh[k][q * 128];
        unsigned long long a0 = 0ULL, a1 = 0ULL, a2 = 0ULL, a3 = 0ULL;
        #pragma unroll
        for (int i = 0; i < 16; i++) {
            ulonglong2 hv1 = h4[2 * i];
            ulonglong2 hv2 = h4[2 * i + 1];
            a0 = fma2(R2[4 * i + 0], hv1.x, a0);
            a1 = fma2(R2[4 * i + 1], hv1.y, a1);
            a2 = fma2(R2[4 * i + 2], hv2.x, a2);
            a3 = fma2(R2[4 * i + 3], hv2.y, a3);
        }
        partial[q][c] = hsum2(add2(add2(a0, a1), add2(a2, a3)));
        __syncthreads();

        if (tid < 64) {
            // prefetch next step's xb (hidden behind gates + exchange)
            float nxz = 0.f, nxr = 0.f, nxh = 0.f;
            if (t + 1 < TT) {
                const float* nxb = xb + (size_t)(t + 1) * 192;
                nxz = nxb[tid]; nxr = nxb[64 + tid]; nxh = nxb[128 + tid];
            }
            float rz = partial[0][tid]       + partial[1][tid]       + rbz;
            float rr = partial[0][64 + tid]  + partial[1][64 + tid]  + rbr;
            float rh = partial[0][128 + tid] + partial[1][128 + tid] + rbh;
            float z  = sigmoid_fast(xz + rz);
            float r  = sigmoid_fast(xr + rr);
            float hh = tanh_fast(xh + r * rh);
            float hp = h_sh[k][rank * 64 + tid];
            float hn = z * hp + (1.f - z) * hh;

            if (flags & 1) seqp[(size_t)t * HH + tid] = hn;

            // gather 4 consecutive h values into lanes lane%4==0 via shuffles
            float v1 = __shfl_down_sync(~0u, hn, 1);
            float v2 = __shfl_down_sync(~0u, hn, 2);
            float v3 = __shfl_down_sync(~0u, hn, 3);

            if (((tid & 3) == 0) && ((flags & 2) || t + 1 < TT)) {
                float4 pkt = make_float4(hn, v1, v2, v3);
                uint32_t boff = (uint32_t)(((k ^ 1) * 256 + rank * 64 + tid) << 2);
                uint32_t moff = (uint32_t)((k ^ 1) * 8);
                #pragma unroll
                for (int tg = 0; tg < 4; tg++)
                    st_async_v4(rhb[tg] + boff, pkt, rmb[tg] + moff);
            }
            xz = nxz; xr = nxr; xh = nxh;
        }
        // no CTA-wide barrier: the next mbar_wait provides the sync
    }

    // dense head (GRU2): wait final exchange X_TT (on mbar[0], parity ph0)
    if (flags & 2) {
        mbar_wait(mb0, ph0);
        if (rank == 0 && tid < 64) {
            float acc = bd[tid];
            #pragma unroll 8
            for (int kk2 = 0; kk2 < 256; kk2++) acc += h_sh[0][kk2] * wd[kk2 * 64 + tid];
            out[b * 64 + tid] = acc;
        }
    }
}

// ---------------- launch ----------------
extern "C" void kernel_launch(void* const* d_in, const int* in_sizes, int n_in,
                              void* d_out, int out_size)
{
    const float* x     = (const float*)d_in[0];
    const float* gamma = (const float*)d_in[1];
    const float* beta  = (const float*)d_in[2];
    const float* k1    = (const float*)d_in[3];
    const float* rk1   = (const float*)d_in[4];
    const float* b1    = (const float*)d_in[5];   // [2,768]
    const float* k2    = (const float*)d_in[6];
    const float* rk2   = (const float*)d_in[7];
    const float* b2    = (const float*)d_in[8];   // [2,768]
    const float* wd    = (const float*)d_in[9];
    const float* bd    = (const float*)d_in[10];
    float* out = (float*)d_out;

    (void)in_sizes; (void)n_in; (void)out_size;

    ln_kernel<<<ROWS / 8, 256>>>(x, gamma, beta);
    proj_kernel<<<dim3(G3 / 128, ROWS / 128), 256>>>(FF, 0, k1, b1);
    gru_kernel<<<dim3(4, BB), 384>>>(rk1, b1 + G3, wd, bd, out, /*flags=*/1);
    proj_kernel<<<dim3(G3 / 128, ROWS / 128), 256>>>(HH, 1, k2, b2);
    gru_kernel<<<dim3(4, BB), 384>>>(rk2, b2 + G3, wd, bd, out, /*flags=*/2);
}

// round 12
// speedup vs baseline: 1.1201x; 1.0941x over previous
#include <cuda_runtime.h>
#include <cuda_bf16.h>
#include <cstdint>

// Problem dims
#define BB   32
#define TT   2048
#define FF   64
#define HH   256
#define OUTD 64
#define ROWS (BB*TT)          // 65536
#define G3   (3*HH)           // 768
#define TK   32               // proj k-chunk

// ---------------- scratch (static device globals; no allocation) ----------------
__device__ float g_xn [ (size_t)ROWS * FF ];     // 16 MB  LayerNorm output
__device__ float g_xbR[ (size_t)ROWS * G3 ];     // 192 MB rearranged xb (reused by both GRUs)
__device__ float g_h1 [ (size_t)ROWS * HH ];     // 64 MB  GRU1 sequence output

// ---------------- helpers ----------------
__device__ __forceinline__ uint32_t smem_u32(const void* p) {
    uint32_t a;
    asm("{ .reg .u64 t; cvta.to.shared.u64 t, %1; cvt.u32.u64 %0, t; }" : "=r"(a) : "l"(p));
    return a;
}
__device__ __forceinline__ unsigned long long pack2(float lo, float hi) {
    unsigned long long r;
    asm("mov.b64 %0, {%1, %2};" : "=l"(r) : "f"(lo), "f"(hi));
    return r;
}
__device__ __forceinline__ unsigned long long fma2(unsigned long long a, unsigned long long b,
                                                   unsigned long long c) {
    unsigned long long d;
    asm("fma.rn.f32x2 %0, %1, %2, %3;" : "=l"(d) : "l"(a), "l"(b), "l"(c));
    return d;
}
__device__ __forceinline__ unsigned long long add2(unsigned long long a, unsigned long long b) {
    unsigned long long d;
    asm("add.rn.f32x2 %0, %1, %2;" : "=l"(d) : "l"(a), "l"(b));
    return d;
}
__device__ __forceinline__ float hsum2(unsigned long long a) {
    float lo, hi;
    asm("mov.b64 {%0, %1}, %2;" : "=f"(lo), "=f"(hi) : "l"(a));
    return lo + hi;
}
__device__ __forceinline__ void unpack2(unsigned long long a, float& lo, float& hi) {
    asm("mov.b64 {%0, %1}, %2;" : "=f"(lo), "=f"(hi) : "l"(a));
}
__device__ __forceinline__ float tanh_fast(float x) {
    float y;
    asm("tanh.approx.f32 %0, %1;" : "=f"(y) : "f"(x));
    return y;
}
__device__ __forceinline__ float sigmoid_fast(float x) {
    return 0.5f * tanh_fast(0.5f * x) + 0.5f;
}
__device__ __forceinline__ void mbar_init(uint32_t a, uint32_t cnt) {
    asm volatile("mbarrier.init.shared.b64 [%0], %1;" :: "r"(a), "r"(cnt) : "memory");
}
__device__ __forceinline__ void mbar_expect(uint32_t a, uint32_t tx) {
    asm volatile("mbarrier.arrive.expect_tx.shared.b64 _, [%0], %1;" :: "r"(a), "r"(tx) : "memory");
}
__device__ __forceinline__ void mbar_wait(uint32_t addr, int phase) {
    asm volatile(
        "{\n\t.reg .pred P;\n\t"
        "WL_%=:\n\t"
        "mbarrier.try_wait.parity.acquire.cta.shared::cta.b64 P, [%0], %1, 0x989680;\n\t"
        "@P bra.uni WD_%=;\n\t"
        "bra.uni WL_%=;\n\t"
        "WD_%=:\n\t}"
        :: "r"(addr), "r"(phase) : "memory");
}
__device__ __forceinline__ uint32_t mapa_u32(uint32_t a, uint32_t rnk) {
    uint32_t r;
    asm("mapa.shared::cluster.u32 %0, %1, %2;" : "=r"(r) : "r"(a), "r"(rnk));
    return r;
}
__device__ __forceinline__ void st_async_v4(uint32_t addr, float4 v, uint32_t mbar) {
    asm volatile(
        "st.async.weak.shared::cluster.mbarrier::complete_tx::bytes.v4.b32 "
        "[%0], {%1, %2, %3, %4}, [%5];"
        :: "r"(addr), "f"(v.x), "f"(v.y), "f"(v.z), "f"(v.w), "r"(mbar) : "memory");
}

// ---------------- LayerNorm: one warp per row of 64 ----------------
__global__ __launch_bounds__(256) void ln_kernel(
    const float* __restrict__ x, const float* __restrict__ gamma,
    const float* __restrict__ beta)
{
    int warp = (blockIdx.x * blockDim.x + threadIdx.x) >> 5;
    int lane = threadIdx.x & 31;
    if (warp >= ROWS) return;
    const float* row = x + (size_t)warp * FF;
    float2 v = *(const float2*)&row[lane * 2];
    float s = v.x + v.y;
    #pragma unroll
    for (int o = 16; o; o >>= 1) s += __shfl_xor_sync(~0u, s, o);
    float mu = s * (1.f / 64.f);
    float d0 = v.x - mu, d1 = v.y - mu;
    float q = d0 * d0 + d1 * d1;
    #pragma unroll
    for (int o = 16; o; o >>= 1) q += __shfl_xor_sync(~0u, q, o);
    float rs = rsqrtf(q * (1.f / 64.f) + 1e-3f);
    float2 g  = *(const float2*)&gamma[lane * 2];
    float2 bb = *(const float2*)&beta[lane * 2];
    float2 o2;
    o2.x = d0 * rs * g.x + bb.x;
    o2.y = d1 * rs * g.y + bb.y;
    *(float2*)&g_xn[(size_t)warp * FF + lane * 2] = o2;
}

// ---------------- projection GEMM: C[ROWS,768] = A[ROWS,K] @ W[K,768] + bias ----------------
// Tile 128 rows x 128 cols, k-chunk 32, 256 threads, 8m x 8n per thread (packed-m f32x2).
__global__ __launch_bounds__(256, 2) void proj_kernel(
    int K, int use_h1, const float* __restrict__ W, const float* __restrict__ bias)
{
    __shared__ float As[TK][132];  // [k][m] transposed
    __shared__ float Ws[TK][128];  // [k][n]

    const float* A = use_h1 ? g_h1 : g_xn;
    int cb = blockIdx.x * 128;
    int rb = blockIdx.y * 128;
    int tid  = threadIdx.x;
    int trow = tid >> 4;        // 0..15  (m group of 8)
    int tcol = tid & 15;        // 0..15  (n group of 8)

    // load indices
    int arow = tid >> 3;         // 0..31
    int akq  = (tid & 7) * 4;    // k offset within chunk
    int wkr  = tid >> 5;         // 0..7
    int wc4  = (tid & 31) * 4;   // n offset

    unsigned long long acc[4][8];  // [m-pair][n]
    #pragma unroll
    for (int i = 0; i < 4; i++)
        #pragma unroll
        for (int j = 0; j < 8; j++) acc[i][j] = 0ULL;

    float4 ra[4], rw[4];
    // prefetch chunk 0
    #pragma unroll
    for (int it = 0; it < 4; it++)
        ra[it] = *(const float4*)&A[(size_t)(rb + arow + it * 32) * K + akq];
    #pragma unroll
    for (int it = 0; it < 4; it++)
        rw[it] = *(const float4*)&W[(size_t)(wkr + it * 8) * G3 + cb + wc4];

    for (int kk = 0; kk < K; kk += TK) {
        // stage regs -> smem
        #pragma unroll
        for (int it = 0; it < 4; it++) {
            int r = arow + it * 32;
            As[akq + 0][r] = ra[it].x;
            As[akq + 1][r] = ra[it].y;
            As[akq + 2][r] = ra[it].z;
            As[akq + 3][r] = ra[it].w;
            *(float4*)&Ws[wkr + it * 8][wc4] = rw[it];
        }
        __syncthreads();
        // prefetch next chunk
        if (kk + TK < K) {
            #pragma unroll
            for (int it = 0; it < 4; it++)
                ra[it] = *(const float4*)&A[(size_t)(rb + arow + it * 32) * K + kk + TK + akq];
            #pragma unroll
            for (int it = 0; it < 4; it++)
                rw[it] = *(const float4*)&W[(size_t)(kk + TK + wkr + it * 8) * G3 + cb + wc4];
        }
        #pragma unroll 8
        for (int k = 0; k < TK; k++) {
            const ulonglong2* ap = (const ulonglong2*)&As[k][trow * 8];
            ulonglong2 a01 = ap[0], a23 = ap[1];
            float4 b0 = *(const float4*)&Ws[k][tcol * 8];
            float4 b1 = *(const float4*)&Ws[k][tcol * 8 + 4];
            unsigned long long bb[8];
            bb[0] = pack2(b0.x, b0.x); bb[1] = pack2(b0.y, b0.y);
            bb[2] = pack2(b0.z, b0.z); bb[3] = pack2(b0.w, b0.w);
            bb[4] = pack2(b1.x, b1.x); bb[5] = pack2(b1.y, b1.y);
            bb[6] = pack2(b1.z, b1.z); bb[7] = pack2(b1.w, b1.w);
            #pragma unroll
            for (int j = 0; j < 8; j++) {
                acc[0][j] = fma2(a01.x, bb[j], acc[0][j]);
                acc[1][j] = fma2(a01.y, bb[j], acc[1][j]);
                acc[2][j] = fma2(a23.x, bb[j], acc[2][j]);
                acc[3][j] = fma2(a23.y, bb[j], acc[3][j]);
            }
        }
        __syncthreads();
    }

    // epilogue: bias + rearranged float4 stores (8 consecutive cc per row)
    int g0   = cb + tcol * 8;
    int gate = g0 >> 8;
    int unit = g0 & 255;
    int rnk  = unit >> 6;
    int cc   = gate * 64 + (unit & 63);
    float bv[8];
    #pragma unroll
    for (int j = 0; j < 8; j++) bv[j] = bias[g0 + j];

    #pragma unroll
    for (int i2 = 0; i2 < 4; i2++) {
        float r0[8], r1[8];
        #pragma unroll
        for (int j = 0; j < 8; j++) {
            unpack2(acc[i2][j], r0[j], r1[j]);
            r0[j] += bv[j]; r1[j] += bv[j];
        }
        #pragma unroll
        for (int half = 0; half < 2; half++) {
            int row = rb + trow * 8 + 2 * i2 + half;
            int b   = row >> 11;
            int t   = row & 2047;
            float* dst = g_xbR + (((size_t)(b * 4 + rnk)) * TT + t) * 192 + cc;
            const float* rv = half ? r1 : r0;
            *(float4*)dst       = make_float4(rv[0], rv[1], rv[2], rv[3]);
            *(float4*)(dst + 4) = make_float4(rv[4], rv[5], rv[6], rv[7]);
        }
    }
}

// ---------------- GRU recurrence: cluster of 4 CTAs per batch ----------------
// 384 threads: q = tid/192 (k-half of 128), c = tid%192 (gate*64+unit).
// R slice in packed f32x2 registers; h double-buffered in SMEM.
// Exchange: gates STS h_new locally (own copy), full-CTA barrier, then 48 sender
// threads spread over all 12 warps each send one st.async.v4 (16 B) to one of the
// 3 REMOTE CTAs (48 msgs/step total; remote mbar sees 48 events, expect_tx=768 B).
__global__ void __cluster_dims__(4, 1, 1) __launch_bounds__(384, 1)
gru_kernel(const float* __restrict__ rk, const float* __restrict__ rbias,
           const float* __restrict__ wd, const float* __restrict__ bd,
           float* __restrict__ out, int flags)  // bit0: write seq to g_h1, bit1: dense head
{
    __shared__ __align__(16) float h_sh[2][256];
    __shared__ float partial[2][192];
    __shared__ __align__(8) unsigned long long mbar[2];

    int tid  = threadIdx.x;
    int rank = blockIdx.x;      // cluster rank
    int b    = blockIdx.y;
    int q    = tid / 192;
    int c    = tid % 192;
    int gate = c >> 6;
    int u    = c & 63;
    int gcol = gate * 256 + rank * 64 + u;

    // load R slice into packed registers: R2[i] = (rk[2i], rk[2i+1]) down column gcol
    unsigned long long R2[64];
    #pragma unroll
    for (int i = 0; i < 64; i++) {
        float lo = rk[(size_t)(q * 128 + 2 * i)     * G3 + gcol];
        float hi = rk[(size_t)(q * 128 + 2 * i + 1) * G3 + gcol];
        R2[i] = pack2(lo, hi);
    }

    uint32_t mb0 = smem_u32(&mbar[0]);
    uint32_t mb1 = smem_u32(&mbar[1]);
    uint32_t hb  = smem_u32(&h_sh[0][0]);

    if (tid == 0) {
        mbar_init(mb0, 1);
        mbar_init(mb1, 1);
        mbar_expect(mb1, 768);    // X_1: 3 remote sources x 256 B
    }
    for (int i = tid; i < 256; i += 384) h_sh[0][i] = 0.f;  // h_0 = 0 in buf 0
    __syncthreads();
    asm volatile("barrier.cluster.arrive.aligned;" ::: "memory");
    asm volatile("barrier.cluster.wait.aligned;"   ::: "memory");

    // sender mapping: threads with tid%8==0 -> s = tid/8 in 0..47
    //   target = (rank + 1 + s/16) & 3  (3 remote CTAs), chunk = s%16 (4 floats)
    int  is_sender = ((tid & 7) == 0);
    int  s_idx   = tid >> 3;
    int  s_tgt   = (rank + 1 + (s_idx >> 4)) & 3;
    int  s_chunk = s_idx & 15;
    uint32_t s_rmb = 0, s_rhb = 0;
    if (is_sender) {
        s_rmb = mapa_u32(mb0, s_tgt);
        s_rhb = mapa_u32(hb, s_tgt);
    }

    const float* xb = g_xbR + ((size_t)(b * 4 + rank)) * TT * 192;
    float rbz = 0.f, rbr = 0.f, rbh = 0.f, xz = 0.f, xr = 0.f, xh = 0.f;
    if (tid < 64) {
        rbz = rbias[rank * 64 + tid];
        rbr = rbias[256 + rank * 64 + tid];
        rbh = rbias[512 + rank * 64 + tid];
        xz = xb[tid]; xr = xb[64 + tid]; xh = xb[128 + tid];
    }

    float* seqp = g_h1 + ((size_t)b * TT) * HH + rank * 64;
    int ph0 = 0, ph1 = 0;

    for (int t = 0; t < TT; t++) {
        int k = t & 1;                       // h_t lives in buf[k], exchange on mbar[k]
        if (t) {
            if (k) { mbar_wait(mb1, ph1); ph1 ^= 1; }
            else   { mbar_wait(mb0, ph0); ph0 ^= 1; }
        }
        if (tid == 0 && t + 2 <= TT)
            mbar_expect(k ? mb1 : mb0, 768);    // X_{t+2} on same mbar

        // ---- inner product: 64 packed fma2 per thread
        const ulonglong2* h4 = (const ulonglong2*)&h_sh[k][q * 128];
        unsigned long long a0 = 0ULL, a1 = 0ULL, a2 = 0ULL, a3 = 0ULL;
        #pragma unroll
        for (int i = 0; i < 16; i++) {
            ulonglong2 hv1 = h4[2 * i];
            ulonglong2 hv2 = h4[2 * i + 1];
            a0 = fma2(R2[4 * i + 0], hv1.x, a0);
            a1 = fma2(R2[4 * i + 1], hv1.y, a1);
            a2 = fma2(R2[4 * i + 2], hv2.x, a2);
            a3 = fma2(R2[4 * i + 3], hv2.y, a3);
        }
        partial[q][c] = hsum2(add2(add2(a0, a1), add2(a2, a3)));
        __syncthreads();

        if (tid < 64) {
            // prefetch next step's xb (hidden behind gates + exchange)
            float nxz = 0.f, nxr = 0.f, nxh = 0.f;
            if (t + 1 < TT) {
                const float* nxb = xb + (size_t)(t + 1) * 192;
                nxz = nxb[tid]; nxr = nxb[64 + tid]; nxh = nxb[128 + tid];
            }
            float rz = partial[0][tid]       + partial[1][tid]       + rbz;
            float rr = partial[0][64 + tid]  + partial[1][64 + tid]  + rbr;
            float rh = partial[0][128 + tid] + partial[1][128 + tid] + rbh;
            float z  = sigmoid_fast(xz + rz);
            float r  = sigmoid_fast(xr + rr);
            float hh = tanh_fast(xh + r * rh);
            float hp = h_sh[k][rank * 64 + tid];
            float hn = z * hp + (1.f - z) * hh;

            h_sh[k ^ 1][rank * 64 + tid] = hn;            // local copy (own quarter)
            if (flags & 1) seqp[(size_t)t * HH + tid] = hn;
            xz = nxz; xr = nxr; xh = nxh;
        }
        __syncthreads();   // drains gates' STS; releases senders in all 12 warps

        if (is_sender && ((flags & 2) || t + 1 < TT)) {
            float4 pkt = *(const float4*)&h_sh[k ^ 1][rank * 64 + s_chunk * 4];
            uint32_t boff = (uint32_t)(((k ^ 1) * 256 + rank * 64 + s_chunk * 4) << 2);
            uint32_t moff = (uint32_t)((k ^ 1) * 8);
            st_async_v4(s_rhb + boff, pkt, s_rmb + moff);
        }
        // no further barrier: next mbar_wait + this step's syncthreads provide sync
    }

    // dense head (GRU2): wait final exchange X_TT (on mbar[0], parity ph0)
    if (flags & 2) {
        mbar_wait(mb0, ph0);
        if (rank == 0 && tid < 64) {
            float acc = bd[tid];
            #pragma unroll 8
            for (int kk2 = 0; kk2 < 256; kk2++) acc += h_sh[0][kk2] * wd[kk2 * 64 + tid];
            out[b * 64 + tid] = acc;
        }
    }
}

// ---------------- launch ----------------
extern "C" void kernel_launch(void* const* d_in, const int* in_sizes, int n_in,
                              void* d_out, int out_size)
{
    const float* x     = (const float*)d_in[0];
    const float* gamma = (const float*)d_in[1];
    const float* beta  = (const float*)d_in[2];
    const float* k1    = (const float*)d_in[3];
    const float* rk1   = (const float*)d_in[4];
    const float* b1    = (const float*)d_in[5];   // [2,768]
    const float* k2    = (const float*)d_in[6];
    const float* rk2   = (const float*)d_in[7];
    const float* b2    = (const float*)d_in[8];   // [2,768]
    const float* wd    = (const float*)d_in[9];
    const float* bd    = (const float*)d_in[10];
    float* out = (float*)d_out;

    (void)in_sizes; (void)n_in; (void)out_size;

    ln_kernel<<<ROWS / 8, 256>>>(x, gamma, beta);
    proj_kernel<<<dim3(G3 / 128, ROWS / 128), 256>>>(FF, 0, k1, b1);
    gru_kernel<<<dim3(4, BB), 384>>>(rk1, b1 + G3, wd, bd, out, /*flags=*/1);
    proj_kernel<<<dim3(G3 / 128, ROWS / 128), 256>>>(HH, 1, k2, b2);
    gru_kernel<<<dim3(4, BB), 384>>>(rk2, b2 + G3, wd, bd, out, /*flags=*/2);
}